// round 15
// baseline (speedup 1.0000x reference)
#include <cuda_runtime.h>
#include <cstdint>

#define NUM_ANCHORS 145152
#define NUM_CH 85
#define INV_IMG (1.0f / 1536.0f)
#define ROWS_PER_TILE 64
#define CONSUMER_WARPS 8
#define THREADS ((CONSUMER_WARPS + 1) * 32)            // 288
#define DEPTH 4
#define NUM_TILES (NUM_ANCHORS / ROWS_PER_TILE)        // 2268
#define TILE_FLOATS (ROWS_PER_TILE * NUM_CH)           // 5440
#define TILE_BYTES (TILE_FLOATS * 4)                   // 21760
#define ROWS_PER_WARP (ROWS_PER_TILE / CONSUMER_WARPS) // 8
#define SMEM_BYTES (256 + DEPTH * TILE_BYTES)          // 87296 B

// d_out layout (fp32), reference tuple order, flattened:
//   [0 .. 4N)    bboxes     (N,4) = x0, y0, x1, y1
//   [4N .. 5N)   scores     (N,)
//   [5N .. 6N)   class_pred (N,)  (as float)
//   [6N .. 12N)  detections (N,6) = x0, y0, x1, y1, conf, cls

__device__ __forceinline__ unsigned smem_u32(const void* p) {
    unsigned a;
    asm("{ .reg .u64 t; cvta.to.shared.u64 t, %1; cvt.u32.u64 %0, t; }"
        : "=r"(a) : "l"(p));
    return a;
}

__device__ __forceinline__ void mbar_init(unsigned mbar, unsigned count) {
    asm volatile("mbarrier.init.shared.b64 [%0], %1;" :: "r"(mbar), "r"(count)
                 : "memory");
}

__device__ __forceinline__ void mbar_expect_tx(unsigned mbar, unsigned bytes) {
    asm volatile("mbarrier.arrive.expect_tx.shared.b64 _, [%0], %1;"
                 :: "r"(mbar), "r"(bytes) : "memory");
}

__device__ __forceinline__ void mbar_arrive(unsigned mbar) {
    asm volatile("mbarrier.arrive.shared.b64 _, [%0];" :: "r"(mbar) : "memory");
}

// One-shot bulk copy gmem -> smem (async proxy), completion on mbar.
__device__ __forceinline__ void bulk_load(unsigned dst, const void* src,
                                          unsigned bytes, unsigned mbar) {
    asm volatile(
        "cp.async.bulk.shared::cta.global.mbarrier::complete_tx::bytes "
        "[%0], [%1], %2, [%3];"
        :: "r"(dst), "l"(src), "r"(bytes), "r"(mbar) : "memory");
}

// Acquire wait (consumers: generic smem reads follow).
__device__ __forceinline__ void mbar_wait_acq(unsigned mbar, unsigned phase) {
    asm volatile(
        "{\n\t"
        ".reg .pred P1;\n\t"
        "WL_%=:\n\t"
        "mbarrier.try_wait.parity.acquire.cta.shared::cta.b64 P1, [%0], %1, 0x989680;\n\t"
        "@P1 bra.uni WD_%=;\n\t"
        "bra.uni WL_%=;\n\t"
        "WD_%=:\n\t"
        "}"
        :: "r"(mbar), "r"(phase) : "memory");
}

// Relaxed wait (producer: only async-proxy TMA issue follows).
__device__ __forceinline__ void mbar_wait_rlx(unsigned mbar, unsigned phase) {
    asm volatile(
        "{\n\t"
        ".reg .pred P1;\n\t"
        "WL_%=:\n\t"
        "mbarrier.try_wait.parity.relaxed.cta.shared::cta.b64 P1, [%0], %1, 0x989680;\n\t"
        "@P1 bra.uni WD_%=;\n\t"
        "bra.uni WL_%=;\n\t"
        "WD_%=:\n\t"
        "}"
        :: "r"(mbar), "r"(phase) : "memory");
}

// Quad-lane decode of this warp's 8 rows of a tile: 4 lanes per row,
// each lane scans 20 channels, 2-stage shfl combine.
__device__ __forceinline__ void compute_rows(const float* __restrict__ s_tile,
                                             float* __restrict__ out,
                                             int tile, int cw, int lane)
{
    const unsigned FULL = 0xffffffffu;
    const int row = cw * ROWS_PER_WARP + (lane >> 2);   // warp's own rows
    const int q   = lane & 3;
    const float* s = s_tile + row * NUM_CH;   // stride 85 -> conflict-free
    const int anchor = tile * ROWS_PER_TILE + row;

    // Header (broadcast reads within each 4-lane group).
    float cx  = s[0];
    float cy  = s[1];
    float w   = s[2];
    float h   = s[3];
    float obj = s[4];

    // 20-channel scan per lane, strict > keeps lowest index on ties.
    const int base = 20 * q;
    const float* cs = s + 5 + base;
    float bv = cs[0];
    int   bi = base;
    #pragma unroll
    for (int k = 1; k < 20; ++k) {
        float v = cs[k];
        if (v > bv) { bv = v; bi = base + k; }
    }

    // Combine the four quarters (lowest index wins ties).
    #pragma unroll
    for (int off = 1; off <= 2; off <<= 1) {
        float ov = __shfl_xor_sync(FULL, bv, off);
        int   oi = __shfl_xor_sync(FULL, bi, off);
        if (ov > bv || (ov == bv && oi < bi)) { bv = ov; bi = oi; }
    }

    float bx = cx * INV_IMG;
    float by = cy * INV_IMG;
    float bw = w  * INV_IMG;
    float bh = h  * INV_IMG;
    float x0 = bx - bw * 0.5f;
    float y0 = by - bh * 0.5f;
    float x1 = bx + bw * 0.5f;
    float y1 = by + bh * 0.5f;

    float conf  = bv;
    float clsf  = (float)bi;
    float score = obj * conf;

    float* out_sc  = out + (long long)NUM_ANCHORS * 4;
    float* out_cls = out + (long long)NUM_ANCHORS * 5;
    float* out_det = out + (long long)NUM_ANCHORS * 6;

    // Distribute writes across the 4 group lanes; every stream coalesced.
    if (q == 0) {
        ((float4*)out)[anchor] = make_float4(x0, y0, x1, y1);
    } else if (q == 1) {
        out_sc[anchor]  = score;
        out_cls[anchor] = clsf;
    } else {
        float2* det = (float2*)(out_det + (long long)anchor * 6);
        if (q == 2) {
            det[0] = make_float2(x0, y0);
            det[1] = make_float2(x1, y1);
        } else {
            det[2] = make_float2(conf, clsf);
        }
    }
}

__global__ __launch_bounds__(THREADS)
void yolo_decode_kernel(const float* __restrict__ pred,
                        float* __restrict__ out,
                        int n_blocks_total)
{
    extern __shared__ float smem[];
    char* sbase = (char*)smem;
    // barriers: full[k] at 16k, empty[k] at 16k+8 ; tiles start at +256
    float* tiles = (float*)(sbase + 256);

    const int tid  = threadIdx.x;
    const int wid  = tid >> 5;
    const int lane = tid & 31;

    if (tid == 0) {
        #pragma unroll
        for (int k = 0; k < DEPTH; ++k) {
            mbar_init(smem_u32(sbase + 16 * k),     1);              // full
            mbar_init(smem_u32(sbase + 16 * k + 8), CONSUMER_WARPS); // empty
        }
        asm volatile("fence.proxy.async.shared::cta;" ::: "memory");
    }
    __syncthreads();

    if (blockIdx.x >= NUM_TILES) return;

    if (wid == CONSUMER_WARPS) {
        // ================= PRODUCER (single thread) =================
        if (lane == 0) {
            int slot = 0, phase = 1;   // phase=1: first empty-waits pass
            for (int t = blockIdx.x; t < NUM_TILES; t += n_blocks_total) {
                unsigned fullb  = smem_u32(sbase + 16 * slot);
                unsigned emptyb = smem_u32(sbase + 16 * slot + 8);
                mbar_wait_rlx(emptyb, phase);
                mbar_expect_tx(fullb, TILE_BYTES);
                bulk_load(smem_u32(tiles + slot * TILE_FLOATS),
                          pred + (long long)t * TILE_FLOATS,
                          TILE_BYTES, fullb);
                if (++slot == DEPTH) { slot = 0; phase ^= 1; }
            }
        }
    } else {
        // ================= CONSUMERS (8 warps) ======================
        const int cw = wid;
        int slot = 0, phase = 0;
        for (int t = blockIdx.x; t < NUM_TILES; t += n_blocks_total) {
            unsigned fullb  = smem_u32(sbase + 16 * slot);
            unsigned emptyb = smem_u32(sbase + 16 * slot + 8);
            mbar_wait_acq(fullb, phase);

            compute_rows(tiles + slot * TILE_FLOATS, out, t, cw, lane);

            __syncwarp();
            if (lane == 0) mbar_arrive(emptyb);   // one arrival per warp
            if (++slot == DEPTH) { slot = 0; phase ^= 1; }
        }
    }
}

extern "C" void kernel_launch(void* const* d_in, const int* in_sizes, int n_in,
                              void* d_out, int out_size)
{
    const float* pred = (const float*)d_in[0];
    // d_in[1] = score_threshold — unused by the reference computation.
    float* out = (float*)d_out;

    cudaFuncSetAttribute(yolo_decode_kernel,
                         cudaFuncAttributeMaxDynamicSharedMemorySize,
                         SMEM_BYTES);

    const int blocks = 296;                 // 2 per SM, persistent grid-stride
    yolo_decode_kernel<<<blocks, THREADS, SMEM_BYTES>>>(pred, out, blocks);
}

// round 16
// speedup vs baseline: 1.0652x; 1.0652x over previous
#include <cuda_runtime.h>
#include <cstdint>

#define NUM_ANCHORS 145152
#define NUM_CH 85
#define INV_IMG (1.0f / 1536.0f)
#define ROWS_PER_TILE 64
#define CONSUMER_WARPS 4
#define THREADS ((CONSUMER_WARPS + 1) * 32)            // 160
#define DEPTH 3
#define NUM_TILES (NUM_ANCHORS / ROWS_PER_TILE)        // 2268
#define TILE_FLOATS (ROWS_PER_TILE * NUM_CH)           // 5440
#define TILE_BYTES (TILE_FLOATS * 4)                   // 21760
#define ROWS_PER_WARP (ROWS_PER_TILE / CONSUMER_WARPS) // 16
#define SMEM_BYTES (256 + DEPTH * TILE_BYTES)          // 65536 B -> 3 blocks/SM

// d_out layout (fp32), reference tuple order, flattened:
//   [0 .. 4N)    bboxes     (N,4) = x0, y0, x1, y1
//   [4N .. 5N)   scores     (N,)
//   [5N .. 6N)   class_pred (N,)  (as float)
//   [6N .. 12N)  detections (N,6) = x0, y0, x1, y1, conf, cls

__device__ __forceinline__ unsigned smem_u32(const void* p) {
    unsigned a;
    asm("{ .reg .u64 t; cvta.to.shared.u64 t, %1; cvt.u32.u64 %0, t; }"
        : "=r"(a) : "l"(p));
    return a;
}

__device__ __forceinline__ void mbar_init(unsigned mbar, unsigned count) {
    asm volatile("mbarrier.init.shared.b64 [%0], %1;" :: "r"(mbar), "r"(count)
                 : "memory");
}

__device__ __forceinline__ void mbar_expect_tx(unsigned mbar, unsigned bytes) {
    asm volatile("mbarrier.arrive.expect_tx.shared.b64 _, [%0], %1;"
                 :: "r"(mbar), "r"(bytes) : "memory");
}

__device__ __forceinline__ void mbar_arrive(unsigned mbar) {
    asm volatile("mbarrier.arrive.shared.b64 _, [%0];" :: "r"(mbar) : "memory");
}

// One-shot bulk copy gmem -> smem (async proxy), completion on mbar.
__device__ __forceinline__ void bulk_load(unsigned dst, const void* src,
                                          unsigned bytes, unsigned mbar) {
    asm volatile(
        "cp.async.bulk.shared::cta.global.mbarrier::complete_tx::bytes "
        "[%0], [%1], %2, [%3];"
        :: "r"(dst), "l"(src), "r"(bytes), "r"(mbar) : "memory");
}

// Acquire wait (consumers: generic smem reads follow).
__device__ __forceinline__ void mbar_wait_acq(unsigned mbar, unsigned phase) {
    asm volatile(
        "{\n\t"
        ".reg .pred P1;\n\t"
        "WL_%=:\n\t"
        "mbarrier.try_wait.parity.acquire.cta.shared::cta.b64 P1, [%0], %1, 0x989680;\n\t"
        "@P1 bra.uni WD_%=;\n\t"
        "bra.uni WL_%=;\n\t"
        "WD_%=:\n\t"
        "}"
        :: "r"(mbar), "r"(phase) : "memory");
}

// Relaxed wait (producer: only async-proxy TMA issue follows).
__device__ __forceinline__ void mbar_wait_rlx(unsigned mbar, unsigned phase) {
    asm volatile(
        "{\n\t"
        ".reg .pred P1;\n\t"
        "WL_%=:\n\t"
        "mbarrier.try_wait.parity.relaxed.cta.shared::cta.b64 P1, [%0], %1, 0x989680;\n\t"
        "@P1 bra.uni WD_%=;\n\t"
        "bra.uni WL_%=;\n\t"
        "WD_%=:\n\t"
        "}"
        :: "r"(mbar), "r"(phase) : "memory");
}

// Pair-lane decode of this warp's 16 rows of a tile.
__device__ __forceinline__ void compute_rows(const float* __restrict__ s_tile,
                                             float* __restrict__ out,
                                             int tile, int cw, int lane)
{
    const unsigned FULL = 0xffffffffu;
    const int row  = cw * ROWS_PER_WARP + (lane >> 1);  // warp's own rows
    const int half = lane & 1;
    const float* s = s_tile + row * NUM_CH;   // stride 85 -> conflict-free
    const int anchor = tile * ROWS_PER_TILE + row;

    float cx  = s[0];
    float cy  = s[1];
    float w   = s[2];
    float h   = s[3];
    float obj = s[4];

    // 40-channel scan per lane, strict > keeps lowest index on ties.
    const int base = 40 * half;
    const float* cs = s + 5 + base;
    float bv = cs[0];
    int   bi = base;
    #pragma unroll
    for (int k = 1; k < 40; ++k) {
        float v = cs[k];
        if (v > bv) { bv = v; bi = base + k; }
    }

    // Combine pair halves (lowest index wins ties).
    float ov = __shfl_xor_sync(FULL, bv, 1);
    int   oi = __shfl_xor_sync(FULL, bi, 1);
    if (ov > bv || (ov == bv && oi < bi)) { bv = ov; bi = oi; }

    float bx = cx * INV_IMG;
    float by = cy * INV_IMG;
    float bw = w  * INV_IMG;
    float bh = h  * INV_IMG;
    float x0 = bx - bw * 0.5f;
    float y0 = by - bh * 0.5f;
    float x1 = bx + bw * 0.5f;
    float y1 = by + bh * 0.5f;

    float conf  = bv;
    float clsf  = (float)bi;
    float score = obj * conf;

    float* out_sc  = out + (long long)NUM_ANCHORS * 4;
    float* out_cls = out + (long long)NUM_ANCHORS * 5;
    float* out_det = out + (long long)NUM_ANCHORS * 6;

    if (half == 0) {
        ((float4*)out)[anchor] = make_float4(x0, y0, x1, y1);
        out_sc[anchor]  = score;
        out_cls[anchor] = clsf;
    } else {
        float2* det = (float2*)(out_det + (long long)anchor * 6);
        det[0] = make_float2(x0, y0);
        det[1] = make_float2(x1, y1);
        det[2] = make_float2(conf, clsf);
    }
}

__global__ __launch_bounds__(THREADS)
void yolo_decode_kernel(const float* __restrict__ pred,
                        float* __restrict__ out,
                        int n_blocks_total)
{
    extern __shared__ float smem[];
    char* sbase = (char*)smem;
    // barriers: full[k] at 16k, empty[k] at 16k+8 ; tiles start at +256
    float* tiles = (float*)(sbase + 256);

    const int tid  = threadIdx.x;
    const int wid  = tid >> 5;
    const int lane = tid & 31;

    if (tid == 0) {
        #pragma unroll
        for (int k = 0; k < DEPTH; ++k) {
            mbar_init(smem_u32(sbase + 16 * k),     1);              // full
            mbar_init(smem_u32(sbase + 16 * k + 8), CONSUMER_WARPS); // empty
        }
        asm volatile("fence.proxy.async.shared::cta;" ::: "memory");
    }
    __syncthreads();

    if (blockIdx.x >= NUM_TILES) return;

    if (wid == CONSUMER_WARPS) {
        // ================= PRODUCER (single thread) =================
        if (lane == 0) {
            int slot = 0, phase = 1;   // phase=1: first empty-waits pass
            for (int t = blockIdx.x; t < NUM_TILES; t += n_blocks_total) {
                unsigned fullb  = smem_u32(sbase + 16 * slot);
                unsigned emptyb = smem_u32(sbase + 16 * slot + 8);
                mbar_wait_rlx(emptyb, phase);
                mbar_expect_tx(fullb, TILE_BYTES);
                bulk_load(smem_u32(tiles + slot * TILE_FLOATS),
                          pred + (long long)t * TILE_FLOATS,
                          TILE_BYTES, fullb);
                if (++slot == DEPTH) { slot = 0; phase ^= 1; }
            }
        }
    } else {
        // ================= CONSUMERS (4 warps) ======================
        const int cw = wid;
        int slot = 0, phase = 0;
        for (int t = blockIdx.x; t < NUM_TILES; t += n_blocks_total) {
            unsigned fullb  = smem_u32(sbase + 16 * slot);
            unsigned emptyb = smem_u32(sbase + 16 * slot + 8);
            mbar_wait_acq(fullb, phase);

            compute_rows(tiles + slot * TILE_FLOATS, out, t, cw, lane);

            __syncwarp();
            if (lane == 0) mbar_arrive(emptyb);   // one arrival per warp
            if (++slot == DEPTH) { slot = 0; phase ^= 1; }
        }
    }
}

extern "C" void kernel_launch(void* const* d_in, const int* in_sizes, int n_in,
                              void* d_out, int out_size)
{
    const float* pred = (const float*)d_in[0];
    // d_in[1] = score_threshold — unused by the reference computation.
    float* out = (float*)d_out;

    cudaFuncSetAttribute(yolo_decode_kernel,
                         cudaFuncAttributeMaxDynamicSharedMemorySize,
                         SMEM_BYTES);

    const int blocks = 444;                 // 3 per SM, persistent grid-stride
    yolo_decode_kernel<<<blocks, THREADS, SMEM_BYTES>>>(pred, out, blocks);
}

// round 17
// speedup vs baseline: 1.2473x; 1.1709x over previous
#include <cuda_runtime.h>
#include <cstdint>

#define NUM_ANCHORS 145152
#define NUM_CH 85
#define INV_IMG (1.0f / 1536.0f)
#define ROWS_PER_TILE 48
#define CONSUMER_WARPS 3
#define THREADS ((CONSUMER_WARPS + 1) * 32)            // 128
#define DEPTH 3
#define NUM_TILES (NUM_ANCHORS / ROWS_PER_TILE)        // 3024
#define TILE_FLOATS (ROWS_PER_TILE * NUM_CH)           // 4080
#define TILE_BYTES (TILE_FLOATS * 4)                   // 16320
#define ROWS_PER_WARP (ROWS_PER_TILE / CONSUMER_WARPS) // 16
#define SMEM_BYTES (256 + DEPTH * TILE_BYTES)          // 49216 B -> 4 blocks/SM

// d_out layout (fp32), reference tuple order, flattened:
//   [0 .. 4N)    bboxes     (N,4) = x0, y0, x1, y1
//   [4N .. 5N)   scores     (N,)
//   [5N .. 6N)   class_pred (N,)  (as float)
//   [6N .. 12N)  detections (N,6) = x0, y0, x1, y1, conf, cls

__device__ __forceinline__ unsigned smem_u32(const void* p) {
    unsigned a;
    asm("{ .reg .u64 t; cvta.to.shared.u64 t, %1; cvt.u32.u64 %0, t; }"
        : "=r"(a) : "l"(p));
    return a;
}

__device__ __forceinline__ void mbar_init(unsigned mbar, unsigned count) {
    asm volatile("mbarrier.init.shared.b64 [%0], %1;" :: "r"(mbar), "r"(count)
                 : "memory");
}

__device__ __forceinline__ void mbar_expect_tx(unsigned mbar, unsigned bytes) {
    asm volatile("mbarrier.arrive.expect_tx.shared.b64 _, [%0], %1;"
                 :: "r"(mbar), "r"(bytes) : "memory");
}

__device__ __forceinline__ void mbar_arrive(unsigned mbar) {
    asm volatile("mbarrier.arrive.shared.b64 _, [%0];" :: "r"(mbar) : "memory");
}

// One-shot bulk copy gmem -> smem (async proxy), completion on mbar.
__device__ __forceinline__ void bulk_load(unsigned dst, const void* src,
                                          unsigned bytes, unsigned mbar) {
    asm volatile(
        "cp.async.bulk.shared::cta.global.mbarrier::complete_tx::bytes "
        "[%0], [%1], %2, [%3];"
        :: "r"(dst), "l"(src), "r"(bytes), "r"(mbar) : "memory");
}

// Acquire wait (consumers: generic smem reads follow).
__device__ __forceinline__ void mbar_wait_acq(unsigned mbar, unsigned phase) {
    asm volatile(
        "{\n\t"
        ".reg .pred P1;\n\t"
        "WL_%=:\n\t"
        "mbarrier.try_wait.parity.acquire.cta.shared::cta.b64 P1, [%0], %1, 0x989680;\n\t"
        "@P1 bra.uni WD_%=;\n\t"
        "bra.uni WL_%=;\n\t"
        "WD_%=:\n\t"
        "}"
        :: "r"(mbar), "r"(phase) : "memory");
}

// Relaxed wait (producer: only async-proxy TMA issue follows).
__device__ __forceinline__ void mbar_wait_rlx(unsigned mbar, unsigned phase) {
    asm volatile(
        "{\n\t"
        ".reg .pred P1;\n\t"
        "WL_%=:\n\t"
        "mbarrier.try_wait.parity.relaxed.cta.shared::cta.b64 P1, [%0], %1, 0x989680;\n\t"
        "@P1 bra.uni WD_%=;\n\t"
        "bra.uni WL_%=;\n\t"
        "WD_%=:\n\t"
        "}"
        :: "r"(mbar), "r"(phase) : "memory");
}

// Pair-lane decode of this warp's 16 rows of a tile.
__device__ __forceinline__ void compute_rows(const float* __restrict__ s_tile,
                                             float* __restrict__ out,
                                             int tile, int cw, int lane)
{
    const unsigned FULL = 0xffffffffu;
    const int row  = cw * ROWS_PER_WARP + (lane >> 1);  // warp's own rows
    const int half = lane & 1;
    const float* s = s_tile + row * NUM_CH;   // stride 85 -> conflict-free
    const int anchor = tile * ROWS_PER_TILE + row;

    float cx  = s[0];
    float cy  = s[1];
    float w   = s[2];
    float h   = s[3];
    float obj = s[4];

    // 40-channel scan per lane, strict > keeps lowest index on ties.
    const int base = 40 * half;
    const float* cs = s + 5 + base;
    float bv = cs[0];
    int   bi = base;
    #pragma unroll
    for (int k = 1; k < 40; ++k) {
        float v = cs[k];
        if (v > bv) { bv = v; bi = base + k; }
    }

    // Combine pair halves (lowest index wins ties).
    float ov = __shfl_xor_sync(FULL, bv, 1);
    int   oi = __shfl_xor_sync(FULL, bi, 1);
    if (ov > bv || (ov == bv && oi < bi)) { bv = ov; bi = oi; }

    float bx = cx * INV_IMG;
    float by = cy * INV_IMG;
    float bw = w  * INV_IMG;
    float bh = h  * INV_IMG;
    float x0 = bx - bw * 0.5f;
    float y0 = by - bh * 0.5f;
    float x1 = bx + bw * 0.5f;
    float y1 = by + bh * 0.5f;

    float conf  = bv;
    float clsf  = (float)bi;
    float score = obj * conf;

    float* out_sc  = out + (long long)NUM_ANCHORS * 4;
    float* out_cls = out + (long long)NUM_ANCHORS * 5;
    float* out_det = out + (long long)NUM_ANCHORS * 6;

    if (half == 0) {
        ((float4*)out)[anchor] = make_float4(x0, y0, x1, y1);
        out_sc[anchor]  = score;
        out_cls[anchor] = clsf;
    } else {
        float2* det = (float2*)(out_det + (long long)anchor * 6);
        det[0] = make_float2(x0, y0);
        det[1] = make_float2(x1, y1);
        det[2] = make_float2(conf, clsf);
    }
}

__global__ __launch_bounds__(THREADS)
void yolo_decode_kernel(const float* __restrict__ pred,
                        float* __restrict__ out,
                        int n_blocks_total)
{
    extern __shared__ float smem[];
    char* sbase = (char*)smem;
    // barriers: full[k] at 16k, empty[k] at 16k+8 ; tiles start at +256
    float* tiles = (float*)(sbase + 256);

    const int tid  = threadIdx.x;
    const int wid  = tid >> 5;
    const int lane = tid & 31;

    if (tid == 0) {
        #pragma unroll
        for (int k = 0; k < DEPTH; ++k) {
            mbar_init(smem_u32(sbase + 16 * k),     1);              // full
            mbar_init(smem_u32(sbase + 16 * k + 8), CONSUMER_WARPS); // empty
        }
        asm volatile("fence.proxy.async.shared::cta;" ::: "memory");
    }
    __syncthreads();

    if (blockIdx.x >= NUM_TILES) return;

    if (wid == CONSUMER_WARPS) {
        // ================= PRODUCER (single thread) =================
        if (lane == 0) {
            int slot = 0, phase = 1;   // phase=1: first empty-waits pass
            for (int t = blockIdx.x; t < NUM_TILES; t += n_blocks_total) {
                unsigned fullb  = smem_u32(sbase + 16 * slot);
                unsigned emptyb = smem_u32(sbase + 16 * slot + 8);
                mbar_wait_rlx(emptyb, phase);
                mbar_expect_tx(fullb, TILE_BYTES);
                bulk_load(smem_u32(tiles + slot * TILE_FLOATS),
                          pred + (long long)t * TILE_FLOATS,
                          TILE_BYTES, fullb);
                if (++slot == DEPTH) { slot = 0; phase ^= 1; }
            }
        }
    } else {
        // ================= CONSUMERS (3 warps) ======================
        const int cw = wid;
        int slot = 0, phase = 0;
        for (int t = blockIdx.x; t < NUM_TILES; t += n_blocks_total) {
            unsigned fullb  = smem_u32(sbase + 16 * slot);
            unsigned emptyb = smem_u32(sbase + 16 * slot + 8);
            mbar_wait_acq(fullb, phase);

            compute_rows(tiles + slot * TILE_FLOATS, out, t, cw, lane);

            __syncwarp();
            if (lane == 0) mbar_arrive(emptyb);   // one arrival per warp
            if (++slot == DEPTH) { slot = 0; phase ^= 1; }
        }
    }
}

extern "C" void kernel_launch(void* const* d_in, const int* in_sizes, int n_in,
                              void* d_out, int out_size)
{
    const float* pred = (const float*)d_in[0];
    // d_in[1] = score_threshold — unused by the reference computation.
    float* out = (float*)d_out;

    cudaFuncSetAttribute(yolo_decode_kernel,
                         cudaFuncAttributeMaxDynamicSharedMemorySize,
                         SMEM_BYTES);

    const int blocks = 592;                 // 4 per SM, persistent grid-stride
    yolo_decode_kernel<<<blocks, THREADS, SMEM_BYTES>>>(pred, out, blocks);
}